// round 4
// baseline (speedup 1.0000x reference)
#include <cuda_runtime.h>
#include <cuda_bf16.h>
#include <stdint.h>

// Problem shape (fixed by the dataset): N=262144, C=128, D=256
#define NMAX 262144
#define C_CLS 128
#define D_FEAT 256
#define SLICE 16384   // rows per segment-sum slice

// ---------------- scratch (no allocations allowed) ----------------
__device__ unsigned char g_labels[NMAX];
__device__ float g_sums[C_CLS * D_FEAT];
__device__ float g_counts[C_CLS];

// ---------------- K1: zero scratch + per-row argmax -> uint8 label ----------------
// one warp per row; lane reads float4 => 512B coalesced per warp.
// Zeroing is fused here: it runs inside the SAME captured graph node each
// replay, strictly before k_segsum's atomics (stream order), so every graph
// replay is deterministic — same inputs, same output.
__global__ void k_argmax(const float* __restrict__ logits, float* __restrict__ out, int N) {
    const int gtid = blockIdx.x * blockDim.x + threadIdx.x;
    if (gtid < C_CLS * D_FEAT) g_sums[gtid] = 0.0f;
    if (gtid < C_CLS) g_counts[gtid] = 0.0f;
    if (gtid == 0) out[0] = 0.0f;

    const int warp = gtid >> 5;
    const int lane = threadIdx.x & 31;
    if (warp >= N) return;
    const float4* row = (const float4*)(logits + (size_t)warp * C_CLS);
    float4 v = row[lane];
    float m = v.x; int mi = lane * 4;
    if (v.y > m) { m = v.y; mi = lane * 4 + 1; }
    if (v.z > m) { m = v.z; mi = lane * 4 + 2; }
    if (v.w > m) { m = v.w; mi = lane * 4 + 3; }
    #pragma unroll
    for (int off = 16; off > 0; off >>= 1) {
        float om = __shfl_down_sync(0xffffffffu, m, off);
        int   oi = __shfl_down_sync(0xffffffffu, mi, off);
        if (om > m || (om == m && oi < mi)) { m = om; mi = oi; }  // first-index tiebreak
    }
    if (lane == 0) g_labels[warp] = (unsigned char)mi;
}

// ---------------- K2: segment sum via gather ----------------
// grid = (S slices, C classes). Each CTA: scan SLICE labels (uchar4, L2-hot),
// compact matching local row ids to smem list, then coalesced float4 gather of
// exactly those rows into register accumulators; one spread REDG per column.
__global__ __launch_bounds__(256, 4)
void k_segsum(const float* __restrict__ F, int N) {
    __shared__ unsigned short list[SLICE];   // 32KB, worst-case all rows match
    __shared__ int s_cnt;
    __shared__ float red[4][D_FEAT];         // 4KB cross-subgroup reduce

    const int tid = threadIdx.x;
    const int cls = blockIdx.y;
    const int slice_base = blockIdx.x * SLICE;
    const int slice_n = min(SLICE, N - slice_base);
    if (slice_n <= 0) return;

    if (tid == 0) s_cnt = 0;
    __syncthreads();

    // phase 1: scan labels (vectorized uchar4), append matches
    const uchar4* __restrict__ lab4 = (const uchar4*)(g_labels + slice_base);
    const int n4 = slice_n >> 2;
    for (int i = tid; i < n4; i += 256) {
        uchar4 L = lab4[i];
        if (L.x == cls) { int p = atomicAdd(&s_cnt, 1); list[p] = (unsigned short)(i * 4 + 0); }
        if (L.y == cls) { int p = atomicAdd(&s_cnt, 1); list[p] = (unsigned short)(i * 4 + 1); }
        if (L.z == cls) { int p = atomicAdd(&s_cnt, 1); list[p] = (unsigned short)(i * 4 + 2); }
        if (L.w == cls) { int p = atomicAdd(&s_cnt, 1); list[p] = (unsigned short)(i * 4 + 3); }
    }
    for (int i = n4 * 4 + tid; i < slice_n; i += 256) {
        if (g_labels[slice_base + i] == cls) {
            int p = atomicAdd(&s_cnt, 1); list[p] = (unsigned short)i;
        }
    }
    __syncthreads();

    const int nm = s_cnt;
    // phase 2: gather. 256 threads = 4 row-subgroups x 64 float4 columns.
    const int sub = tid >> 6;        // 0..3
    const int col = tid & 63;        // float4 column
    float4 acc = make_float4(0.f, 0.f, 0.f, 0.f);
    int k = sub;
    #pragma unroll 4
    for (; k + 12 < nm; k += 16) {   // 4 independent loads in flight per thread
        int r0 = slice_base + list[k];
        int r1 = slice_base + list[k + 4];
        int r2 = slice_base + list[k + 8];
        int r3 = slice_base + list[k + 12];
        float4 v0 = ((const float4*)(F + (size_t)r0 * D_FEAT))[col];
        float4 v1 = ((const float4*)(F + (size_t)r1 * D_FEAT))[col];
        float4 v2 = ((const float4*)(F + (size_t)r2 * D_FEAT))[col];
        float4 v3 = ((const float4*)(F + (size_t)r3 * D_FEAT))[col];
        acc.x += v0.x + v1.x + v2.x + v3.x;
        acc.y += v0.y + v1.y + v2.y + v3.y;
        acc.z += v0.z + v1.z + v2.z + v3.z;
        acc.w += v0.w + v1.w + v2.w + v3.w;
    }
    for (; k < nm; k += 4) {
        int r = slice_base + list[k];
        float4 v = ((const float4*)(F + (size_t)r * D_FEAT))[col];
        acc.x += v.x; acc.y += v.y; acc.z += v.z; acc.w += v.w;
    }

    red[sub][col * 4 + 0] = acc.x;
    red[sub][col * 4 + 1] = acc.y;
    red[sub][col * 4 + 2] = acc.z;
    red[sub][col * 4 + 3] = acc.w;
    __syncthreads();
    float v = red[0][tid] + red[1][tid] + red[2][tid] + red[3][tid];
    atomicAdd(&g_sums[cls * D_FEAT + tid], v);
    if (tid == 0 && nm > 0) atomicAdd(&g_counts[cls], (float)nm);
}

// ---------------- K3: fused means + normalize + similarity + masked loss ----------------
// 128 CTAs (one per row i of the sim matrix), 256 threads.
// mean_i built in smem; thread j (j<128) streams raw sums row j from L2,
// scales on the fly, computes dot(mean_i, mean_j) and norm_j.
__global__ void k_loss(float* __restrict__ out) {
    __shared__ float s_meani[D_FEAT];
    __shared__ float s_cntv[C_CLS];
    __shared__ float s_sq[D_FEAT];
    __shared__ float s_red[C_CLS];

    const int i = blockIdx.x;
    const int t = threadIdx.x;  // 256 threads

    if (t < C_CLS) s_cntv[t] = g_counts[t];
    __syncthreads();

    const float cnt_i = s_cntv[i];
    const float scale_i = 1.0f / fmaxf(cnt_i, 1.0f);
    const float mi = g_sums[i * D_FEAT + t] * scale_i;
    s_meani[t] = mi;
    s_sq[t] = mi * mi;
    __syncthreads();
    // reduce sum of squares -> norm_i
    for (int off = 128; off > 0; off >>= 1) {
        if (t < off) s_sq[t] += s_sq[t + off];
        __syncthreads();
    }
    const float norm_i = sqrtf(s_sq[0]);
    const float ni = (norm_i > 0.0f) ? norm_i : 1.0f;
    const bool present_i = cnt_i > 0.0f;

    float contrib = 0.0f;
    if (t < C_CLS) {
        const int j = t;
        const float cnt_j = s_cntv[j];
        const float scale_j = 1.0f / fmaxf(cnt_j, 1.0f);
        const float4* __restrict__ rj = (const float4*)(g_sums + (size_t)j * D_FEAT);
        const float4* ri = (const float4*)s_meani;
        float dot = 0.0f, ssq = 0.0f;
        #pragma unroll 8
        for (int k = 0; k < D_FEAT / 4; k++) {
            float4 b = rj[k];
            float4 a = ri[k];
            float bx = b.x * scale_j, by = b.y * scale_j, bz = b.z * scale_j, bw = b.w * scale_j;
            dot += a.x * bx + a.y * by + a.z * bz + a.w * bw;
            ssq += bx * bx + by * by + bz * bz + bw * bw;
        }
        const float norm_j = sqrtf(ssq);
        const float nj = (norm_j > 0.0f) ? norm_j : 1.0f;
        const float sim = dot / (ni * nj);
        const bool present_j = cnt_j > 0.0f;
        contrib = (present_i && present_j && (i != j)) ? (1.0f - sim) : 0.0f;
    }
    if (t < C_CLS) s_red[t] = contrib;
    __syncthreads();
    for (int off = 64; off > 0; off >>= 1) {
        if (t < off) s_red[t] += s_red[t + off];
        __syncthreads();
    }
    if (t == 0) atomicAdd(out, s_red[0]);
}

// ---------------- launch ----------------
extern "C" void kernel_launch(void* const* d_in, const int* in_sizes, int n_in,
                              void* d_out, int out_size) {
    const float* logits = (const float*)d_in[0];
    const float* feats  = (const float*)d_in[1];
    float* out = (float*)d_out;
    const int N = in_sizes[0] / C_CLS;

    // one warp per row, 8 rows per 256-thread block; also zeroes scratch + out
    k_argmax<<<(N + 7) / 8, 256>>>(logits, out, N);

    const int S = (N + SLICE - 1) / SLICE;
    dim3 grid2(S, C_CLS);
    k_segsum<<<grid2, 256>>>(feats, N);

    k_loss<<<C_CLS, 256>>>(out);
}